// round 10
// baseline (speedup 1.0000x reference)
#include <cuda_runtime.h>
#include <cuda_fp16.h>
#include <cstdint>

#define B_   8
#define C_   512
#define S_   2048
#define L_   8921
#define LPAD 8960
#define NLT  70

// ---------------- device scratch ----------------
__device__ __align__(16) __half g_encB[B_][C_][S_];   // [b][c][s]
__device__ __align__(16) __half g_encT[B_][S_][C_];   // [b][s][c]
__device__ __align__(16) __half g_wB[LPAD][C_];
__device__ __align__(16) __half g_P[B_][LPAD][S_];    // exp(scores)
__device__ float g_Zinv[B_][LPAD];

// ---------------- helpers ----------------
__device__ __forceinline__ uint32_t smem_u32(const void* p) {
    uint32_t a;
    asm("{ .reg .u64 t; cvta.to.shared.u64 t, %1; cvt.u32.u64 %0, t; }" : "=r"(a) : "l"(p));
    return a;
}
#define CPA(dst, src) \
    asm volatile("cp.async.cg.shared.global [%0], [%1], 16;" :: "r"(dst), "l"(src))
#define CPC() asm volatile("cp.async.commit_group;" ::: "memory")
#define CPW(n) asm volatile("cp.async.wait_group %0;" :: "n"(n) : "memory")

__device__ __forceinline__ void ldsm4(uint32_t* r, uint32_t addr) {
    asm volatile("ldmatrix.sync.aligned.m8n8.x4.shared.b16 {%0,%1,%2,%3}, [%4];"
        : "=r"(r[0]), "=r"(r[1]), "=r"(r[2]), "=r"(r[3]) : "r"(addr));
}
__device__ __forceinline__ void mma16816(float* d, const uint32_t* a, const uint32_t* b) {
    asm volatile("mma.sync.aligned.m16n8k16.row.col.f32.f16.f16.f32 "
        "{%0,%1,%2,%3}, {%4,%5,%6,%7}, {%8,%9}, {%0,%1,%2,%3};"
        : "+f"(d[0]), "+f"(d[1]), "+f"(d[2]), "+f"(d[3])
        : "r"(a[0]), "r"(a[1]), "r"(a[2]), "r"(a[3]), "r"(b[0]), "r"(b[1]));
}

// ---------------- prep kernels ----------------
__global__ void prep_enc(const float* __restrict__ enc) {
    __shared__ float t[32][33];
    int b = blockIdx.z, c0 = blockIdx.x * 32, s0 = blockIdx.y * 32;
    int tx = threadIdx.x & 31, ty = threadIdx.x >> 5;   // 256 threads: 32x8
    #pragma unroll
    for (int r = 0; r < 4; r++) {
        int c = c0 + ty + 8 * r;
        float v = enc[((size_t)b * C_ + c) * S_ + s0 + tx];
        t[ty + 8 * r][tx] = v;
        g_encB[b][c][s0 + tx] = __float2half(v);
    }
    __syncthreads();
    #pragma unroll
    for (int r = 0; r < 4; r++) {
        int s = s0 + ty + 8 * r;
        g_encT[b][s][c0 + tx] = __float2half(t[tx][ty + 8 * r]);
    }
}
__global__ void prep_w(const float* __restrict__ W) {
    int i = blockIdx.x * blockDim.x + threadIdx.x;
    int l = i >> 9, c = i & (C_ - 1);
    g_wB[l][c] = __float2half(l < L_ ? W[(size_t)l * C_ + c] : 0.0f);
}
__global__ void out_init(const float* __restrict__ b_cls, float* __restrict__ out) {
    int i = blockIdx.x * blockDim.x + threadIdx.x;
    if (i < B_ * L_) out[i] = b_cls[i % L_];
}

// ---------------- K1: scores + exp + Z ----------------
// CTA: 128 labels x 256 s per chunk, K=C=512. 512 threads, 16 warps of 32x64.
// A (W tile) resident; B in a 3-stage circular buffer, ONE barrier per chunk.
#define K1_SB    (512 + 131072)
#define K1_SMEM  (512 + 131072 + 3 * 32768)

__global__ __launch_bounds__(512, 1) void k1_scores() {
    extern __shared__ char sm[];
    float* zs = (float*)sm;
    char* sA = sm + 512;
    const uint32_t sAu = smem_u32(sA), sBu = smem_u32(sm + K1_SB);
    const int tid = threadIdx.x, lane = tid & 31, wid = tid >> 5;
    const int wm = (wid >> 2) * 32, wn = (wid & 3) * 64;
    const int b = blockIdx.y, l0 = blockIdx.x * 128;

    if (tid < 128) zs[tid] = 0.f;

    // stage A: 128x512 -> 8 subtiles [128][64], 16B-XOR swizzled
    #pragma unroll
    for (int j = 0; j < 16; j++) {
        int lin = j * 512 + tid;
        int row = lin >> 6, seg = lin & 63;
        uint4 v = *(const uint4*)&g_wB[l0 + row][seg * 8];
        *(uint4*)(sA + (seg >> 3) * 16384 + row * 128 +
                  (((seg & 7) * 16) ^ ((row & 7) << 4))) = v;
    }
    __syncthreads();

    const int swz   = (lane & 7) << 4;
    const int arow  = lane & 15;                         // A: + wm + mt*16
    const int acolb = (lane >> 4) << 4;                  // A: + k0*2
    const int brow  = (lane & 7) + ((lane >> 4) << 3);   // B: + wn + ng*16
    const int bcolb = ((lane >> 3) & 1) << 4;            // B: + k0*2

    // staging indices for this thread (chunk = 256 rows x 64 cols fp16)
    const int strow = tid >> 1;               // rows 0..255, 2 threads/row
    const int stc0  = (tid & 1) << 2;         // c16 = 0..3 or 4..7

    float acc[2][8][4];
    float zr[2][2];
    #pragma unroll
    for (int mt = 0; mt < 2; mt++) { zr[mt][0] = 0.f; zr[mt][1] = 0.f; }

    // prologue: stage chunk 0 into buf 0
    #pragma unroll
    for (int q = 0; q < 4; q++) {
        int c16 = stc0 + q;
        CPA(sBu + strow * 128 + ((c16 * 16) ^ ((strow & 7) << 4)),
            (const char*)&g_encT[b][strow][c16 * 8]);
    }
    CPC();

    #pragma unroll 1
    for (int it = 0; it < 64; it++) {
        const int n = it >> 3, kk = it & 7;
        const uint32_t bufo = (uint32_t)(it % 3) * 32768u;

        if (kk == 0) {
            #pragma unroll
            for (int mt = 0; mt < 2; mt++)
                #pragma unroll
                for (int nt = 0; nt < 8; nt++)
                    acc[mt][nt][0] = acc[mt][nt][1] = acc[mt][nt][2] = acc[mt][nt][3] = 0.f;
        }

        if (it < 63) {   // stage chunk it+1 into buf (it+1)%3
            const int n2 = (it + 1) >> 3, k2 = (it + 1) & 7;
            const uint32_t bo2 = (uint32_t)((it + 1) % 3) * 32768u;
            #pragma unroll
            for (int q = 0; q < 4; q++) {
                int c16 = stc0 + q;
                CPA(sBu + bo2 + strow * 128 + ((c16 * 16) ^ ((strow & 7) << 4)),
                    (const char*)&g_encT[b][n2 * 256 + strow][k2 * 64 + c16 * 8]);
            }
            CPC();
            CPW(1);
        } else {
            CPW(0);
        }
        __syncthreads();   // single barrier per chunk (3-buffer ring makes the trailing one unnecessary)

        const uint32_t aB = sAu + kk * 16384;
        #pragma unroll
        for (int ks = 0; ks < 4; ks++) {
            const int k0b = ks * 32;
            uint32_t a[2][4], bfr[4][4];
            #pragma unroll
            for (int mt = 0; mt < 2; mt++)
                ldsm4(a[mt], aB + (wm + mt * 16 + arow) * 128 + ((k0b + acolb) ^ swz));
            #pragma unroll
            for (int ng = 0; ng < 4; ng++)
                ldsm4(bfr[ng], sBu + bufo + (wn + ng * 16 + brow) * 128 + ((k0b + bcolb) ^ swz));
            #pragma unroll
            for (int mt = 0; mt < 2; mt++)
                #pragma unroll
                for (int ng = 0; ng < 4; ng++) {
                    mma16816(acc[mt][2 * ng],     a[mt], &bfr[ng][0]);
                    mma16816(acc[mt][2 * ng + 1], a[mt], &bfr[ng][2]);
                }
        }

        if (kk == 7) {     // epilogue: exp, store P, accumulate Z (registers + global only)
            const int sg = n * 256 + wn;
            #pragma unroll
            for (int mt = 0; mt < 2; mt++) {
                const int r0 = l0 + wm + mt * 16 + (lane >> 2);
                #pragma unroll
                for (int nt = 0; nt < 8; nt++) {
                    const int sc = sg + nt * 8 + ((lane & 3) << 1);
                    float e0 = __expf(acc[mt][nt][0]);
                    float e1 = __expf(acc[mt][nt][1]);
                    float e2 = __expf(acc[mt][nt][2]);
                    float e3 = __expf(acc[mt][nt][3]);
                    zr[mt][0] += e0 + e1;
                    zr[mt][1] += e2 + e3;
                    *(__half2*)&g_P[b][r0][sc]     = __floats2half2_rn(e0, e1);
                    *(__half2*)&g_P[b][r0 + 8][sc] = __floats2half2_rn(e2, e3);
                }
            }
        }
    }

    #pragma unroll
    for (int mt = 0; mt < 2; mt++) {
        atomicAdd(&zs[wm + mt * 16 + (lane >> 2)],     zr[mt][0]);
        atomicAdd(&zs[wm + mt * 16 + (lane >> 2) + 8], zr[mt][1]);
    }
    __syncthreads();
    if (tid < 128) g_Zinv[b][l0 + tid] = 1.0f / zs[tid];
}

// ---------------- K2: context + classifier ----------------
// CTA: 128 labels x 256 channels, K=S=2048 in chunks of 64. 512 threads, 16 warps.
// Both operands in 3-stage circular buffers, ONE barrier per chunk.
#define K2_SA    512
#define K2_SB    (512 + 3 * 16384)
#define K2_SMEM  (512 + 3 * 16384 + 3 * 32768)

__global__ __launch_bounds__(512, 1) void k2_context(const float* __restrict__ W_cls,
                                                     float* __restrict__ out) {
    extern __shared__ char sm[];
    float* red = (float*)sm;
    const uint32_t sAu = smem_u32(sm + K2_SA), sBu = smem_u32(sm + K2_SB);
    const int tid = threadIdx.x, lane = tid & 31, wid = tid >> 5;
    const int wm = (wid >> 2) * 32, wn = (wid & 3) * 64;
    const int b = blockIdx.z, l0 = blockIdx.x * 128, c0 = blockIdx.y * 256;

    if (tid < 128) red[tid] = 0.f;

    const int swz   = (lane & 7) << 4;
    const int arow  = lane & 15;
    const int acolb = (lane >> 4) << 4;
    const int brow  = (lane & 7) + ((lane >> 4) << 3);
    const int bcolb = ((lane >> 3) & 1) << 4;

    // staging indices: A chunk 128 rows (4 thr/row), B chunk 256 rows (2 thr/row)
    const int sarow = tid >> 2, sac0 = (tid & 3) << 1;   // A: 2 c16 each
    const int sbrow = tid >> 1, sbc0 = (tid & 1) << 2;   // B: 4 c16 each

    float acc[2][8][4];
    #pragma unroll
    for (int mt = 0; mt < 2; mt++)
        #pragma unroll
        for (int nt = 0; nt < 8; nt++)
            acc[mt][nt][0] = acc[mt][nt][1] = acc[mt][nt][2] = acc[mt][nt][3] = 0.f;

    // prologue: stage chunk 0
    #pragma unroll
    for (int q = 0; q < 2; q++) {
        int c16 = sac0 + q;
        CPA(sAu + sarow * 128 + ((c16 * 16) ^ ((sarow & 7) << 4)),
            (const char*)&g_P[b][l0 + sarow][c16 * 8]);
    }
    #pragma unroll
    for (int q = 0; q < 4; q++) {
        int c16 = sbc0 + q;
        CPA(sBu + sbrow * 128 + ((c16 * 16) ^ ((sbrow & 7) << 4)),
            (const char*)&g_encB[b][c0 + sbrow][c16 * 8]);
    }
    CPC();

    #pragma unroll 1
    for (int it = 0; it < 32; it++) {
        const uint32_t aBuf = (uint32_t)(it % 3) * 16384u;
        const uint32_t bBuf = (uint32_t)(it % 3) * 32768u;

        if (it < 31) {   // stage chunk it+1
            const int s2 = (it + 1) * 64;
            const uint32_t a2 = (uint32_t)((it + 1) % 3) * 16384u;
            const uint32_t b2 = (uint32_t)((it + 1) % 3) * 32768u;
            #pragma unroll
            for (int q = 0; q < 2; q++) {
                int c16 = sac0 + q;
                CPA(sAu + a2 + sarow * 128 + ((c16 * 16) ^ ((sarow & 7) << 4)),
                    (const char*)&g_P[b][l0 + sarow][s2 + c16 * 8]);
            }
            #pragma unroll
            for (int q = 0; q < 4; q++) {
                int c16 = sbc0 + q;
                CPA(sBu + b2 + sbrow * 128 + ((c16 * 16) ^ ((sbrow & 7) << 4)),
                    (const char*)&g_encB[b][c0 + sbrow][s2 + c16 * 8]);
            }
            CPC();
            CPW(1);
        } else {
            CPW(0);
        }
        __syncthreads();   // single barrier per chunk

        #pragma unroll
        for (int ks = 0; ks < 4; ks++) {
            const int k0b = ks * 32;
            uint32_t a[2][4], bfr[4][4];
            #pragma unroll
            for (int mt = 0; mt < 2; mt++)
                ldsm4(a[mt], sAu + aBuf + (wm + mt * 16 + arow) * 128 + ((k0b + acolb) ^ swz));
            #pragma unroll
            for (int ng = 0; ng < 4; ng++)
                ldsm4(bfr[ng], sBu + bBuf + (wn + ng * 16 + brow) * 128 + ((k0b + bcolb) ^ swz));
            #pragma unroll
            for (int mt = 0; mt < 2; mt++)
                #pragma unroll
                for (int ng = 0; ng < 4; ng++) {
                    mma16816(acc[mt][2 * ng],     a[mt], &bfr[ng][0]);
                    mma16816(acc[mt][2 * ng + 1], a[mt], &bfr[ng][2]);
                }
        }
    }

    // epilogue: diagonal classifier dot + CTA reduce + global atomic
    #pragma unroll
    for (int mt = 0; mt < 2; mt++) {
        const int lloc = wm + mt * 16 + (lane >> 2);
        const int gl0 = l0 + lloc, gl1 = gl0 + 8;
        float v0 = 0.f, v1 = 0.f;
        #pragma unroll
        for (int nt = 0; nt < 8; nt++) {
            const int c = c0 + wn + nt * 8 + ((lane & 3) << 1);
            if (gl0 < L_) {
                const float* w = &W_cls[(size_t)gl0 * C_ + c];
                v0 += acc[mt][nt][0] * w[0] + acc[mt][nt][1] * w[1];
            }
            if (gl1 < L_) {
                const float* w = &W_cls[(size_t)gl1 * C_ + c];
                v1 += acc[mt][nt][2] * w[0] + acc[mt][nt][3] * w[1];
            }
        }
        atomicAdd(&red[lloc],     v0);
        atomicAdd(&red[lloc + 8], v1);
    }
    __syncthreads();
    if (tid < 128) {
        const int gl = l0 + tid;
        if (gl < L_)
            atomicAdd(&out[(size_t)b * L_ + gl], red[tid] * g_Zinv[b][gl]);
    }
}

// ---------------- launcher ----------------
extern "C" void kernel_launch(void* const* d_in, const int* in_sizes, int n_in,
                              void* d_out, int out_size) {
    const float* encoded = (const float*)d_in[0];
    const float* W_attn  = (const float*)d_in[1];
    // d_in[2] = b_attn: constant along the softmax axis -> no effect on output
    const float* W_cls   = (const float*)d_in[3];
    const float* b_cls   = (const float*)d_in[4];
    float* out = (float*)d_out;

    cudaFuncSetAttribute(k1_scores,  cudaFuncAttributeMaxDynamicSharedMemorySize, K1_SMEM);
    cudaFuncSetAttribute(k2_context, cudaFuncAttributeMaxDynamicSharedMemorySize, K2_SMEM);

    prep_enc<<<dim3(C_ / 32, S_ / 32, B_), 256>>>(encoded);
    prep_w<<<(LPAD * C_) / 256, 256>>>(W_attn);
    out_init<<<(B_ * L_ + 255) / 256, 256>>>(b_cls, out);
    k1_scores<<<dim3(NLT, B_), 512, K1_SMEM>>>();
    k2_context<<<dim3(NLT, 2, B_), 512, K2_SMEM>>>(W_cls, out);
}